// round 2
// baseline (speedup 1.0000x reference)
#include <cuda_runtime.h>

#define IN_F   128
#define HEADS  8
#define HC     16   // HEADS * OUT_C
#define NMAX   100000
#define EMAX   3200000

// Static scratch (no allocations allowed)
__device__ __align__(16) float  g_h[NMAX * HC];       // transformed features [N,16]
__device__ __align__(16) float  g_asrc[NMAX * HEADS]; // alpha_src per node [N,8]
__device__ __align__(16) float  g_adst[NMAX * HEADS]; // alpha_dst per node [N,8]
__device__ float4 g_acc[NMAX * HEADS];                // {S0, S1, Z, 0} per (node, head)

// -------- Kernel 1: per-node transform + self-loop init --------
// warp per node: h[n] = x[n] @ W ; a_src/a_dst ; init g_acc with self-loop term.
__global__ void node_kernel(const float* __restrict__ x,
                            const float* __restrict__ W,
                            const float* __restrict__ att_src,
                            const float* __restrict__ att_dst,
                            int N) {
    __shared__ float Ws[HC * IN_F];   // Ws[j*128 + k] = W[k*16 + j] (transposed)
    __shared__ float s_as[HC], s_ad[HC];
    int tid = threadIdx.x;
    for (int i = tid; i < HC * IN_F; i += blockDim.x) {
        int j = i / IN_F, k = i % IN_F;
        Ws[i] = W[k * HC + j];
    }
    if (tid < HC) { s_as[tid] = att_src[tid]; s_ad[tid] = att_dst[tid]; }
    __syncthreads();

    int warp = tid >> 5, lane = tid & 31;
    int n = blockIdx.x * (blockDim.x >> 5) + warp;
    if (n >= N) return;

    float xv[4];
#pragma unroll
    for (int kk = 0; kk < 4; kk++) xv[kk] = x[(long long)n * IN_F + lane + 32 * kk];

    float acc[HC];
#pragma unroll
    for (int j = 0; j < HC; j++) acc[j] = 0.f;
#pragma unroll
    for (int kk = 0; kk < 4; kk++) {
        int k = lane + 32 * kk;   // lanes contiguous in k -> conflict-free LDS
#pragma unroll
        for (int j = 0; j < HC; j++) acc[j] += xv[kk] * Ws[j * IN_F + k];
    }
    // butterfly reduce: all lanes end with full 16-vector
#pragma unroll
    for (int off = 16; off; off >>= 1) {
#pragma unroll
        for (int j = 0; j < HC; j++) acc[j] += __shfl_xor_sync(0xffffffffu, acc[j], off);
    }

    if (lane < HC) g_h[n * HC + lane] = acc[lane];
    if (lane < HEADS) {
        float h0 = acc[2 * lane], h1 = acc[2 * lane + 1];
        float as = h0 * s_as[2 * lane] + h1 * s_as[2 * lane + 1];
        float ad = h0 * s_ad[2 * lane] + h1 * s_ad[2 * lane + 1];
        g_asrc[n * HEADS + lane] = as;
        g_adst[n * HEADS + lane] = ad;
        // self-loop contribution (src == dst == n)
        float l = as + ad;
        l = (l > 0.f) ? l : 0.2f * l;
        float p = __expf(l);
        g_acc[n * HEADS + lane] = make_float4(p * h0, p * h1, p, 0.f);
    }
}

// -------- Kernel 2: per-edge gather + exp + scatter (vector red) --------
// NOTE: edge_index is int32 on device (JAX default x64-disabled downcasts int64).
__global__ void edge_kernel(const int* __restrict__ ei, int E) {
    int e = blockIdx.x * blockDim.x + threadIdx.x;
    if (e >= E) return;
    int s = ei[e];
    int d = ei[E + e];

    const float4* asp = (const float4*)&g_asrc[(long long)s * HEADS];
    const float4* adp = (const float4*)&g_adst[(long long)d * HEADS];
    float4 a0 = asp[0], a1 = asp[1];
    float4 b0 = adp[0], b1 = adp[1];
    float lg[8] = { a0.x + b0.x, a0.y + b0.y, a0.z + b0.z, a0.w + b0.w,
                    a1.x + b1.x, a1.y + b1.y, a1.z + b1.z, a1.w + b1.w };

    const float4* hp = (const float4*)&g_h[(long long)s * HC];
    float4 h0 = hp[0], h1 = hp[1], h2 = hp[2], h3 = hp[3];
    float hv[16] = { h0.x, h0.y, h0.z, h0.w, h1.x, h1.y, h1.z, h1.w,
                     h2.x, h2.y, h2.z, h2.w, h3.x, h3.y, h3.z, h3.w };

    float4* accp = &g_acc[(long long)d * HEADS];
#pragma unroll
    for (int hh = 0; hh < HEADS; hh++) {
        float l = lg[hh];
        l = (l > 0.f) ? l : 0.2f * l;
        float p = __expf(l);
        float s0 = p * hv[2 * hh], s1 = p * hv[2 * hh + 1];
        asm volatile("red.global.add.v4.f32 [%0], {%1, %2, %3, %4};"
                     :: "l"(accp + hh), "f"(s0), "f"(s1), "f"(p), "f"(0.f)
                     : "memory");
    }
}

// -------- Kernel 3: normalize + bias + FC --------
__global__ void out_kernel(const float* __restrict__ bias_gat,
                           const float* __restrict__ W_fc,
                           const float* __restrict__ b_fc,
                           float* __restrict__ out, int N) {
    int n = blockIdx.x * blockDim.x + threadIdx.x;
    if (n >= N) return;
    float o0 = b_fc[0], o1 = b_fc[1];
#pragma unroll
    for (int hh = 0; hh < HEADS; hh++) {
        float4 a = g_acc[n * HEADS + hh];
        float inv = 1.f / a.z;   // Z >= exp(self-loop) > 0 always
        float g0 = a.x * inv + bias_gat[2 * hh];
        float g1 = a.y * inv + bias_gat[2 * hh + 1];
        o0 += g0 * W_fc[(2 * hh) * 2 + 0] + g1 * W_fc[(2 * hh + 1) * 2 + 0];
        o1 += g0 * W_fc[(2 * hh) * 2 + 1] + g1 * W_fc[(2 * hh + 1) * 2 + 1];
    }
    ((float2*)out)[n] = make_float2(o0, o1);
}

extern "C" void kernel_launch(void* const* d_in, const int* in_sizes, int n_in,
                              void* d_out, int out_size) {
    const float* x        = (const float*)d_in[0];
    const int*   ei       = (const int*)d_in[1];   // int32 (JAX x64 disabled)
    // d_in[2] = edge_attr: unused (GATConv built without edge_dim)
    const float* W        = (const float*)d_in[3];
    const float* att_src  = (const float*)d_in[4];
    const float* att_dst  = (const float*)d_in[5];
    const float* bias_gat = (const float*)d_in[6];
    const float* W_fc     = (const float*)d_in[7];
    const float* b_fc     = (const float*)d_in[8];

    int N = in_sizes[0] / IN_F;
    int E = in_sizes[1] / 2;

    node_kernel<<<(N + 7) / 8, 256>>>(x, W, att_src, att_dst, N);
    edge_kernel<<<(E + 255) / 256, 256>>>(ei, E);
    out_kernel<<<(N + 255) / 256, 256>>>(bias_gat, W_fc, b_fc, (float*)d_out, N);
}

// round 3
// speedup vs baseline: 1.3297x; 1.3297x over previous
#include <cuda_runtime.h>

#define IN_F   128
#define HEADS  8
#define HC     16   // HEADS * OUT_C
#define NMAX   100000

// Static scratch (no allocations allowed)
__device__ __align__(16) float g_h[NMAX * HC];       // transformed features [N,16]
__device__ __align__(16) float g_asrc[NMAX * HEADS]; // alpha_src per node [N,8]
__device__ __align__(16) float g_adst[NMAX * HEADS]; // alpha_dst per node [N,8]
__device__ __align__(16) float g_acc[NMAX * 24];     // per node: S[16] then Z[8]

// FFMA-only exp: exp(x) = 2^(x*log2e); split int/frac, deg-5 Taylor for 2^f,
// exponent injected via integer add on float bits. |x| <= ~20 here, rel err ~2e-6.
__device__ __forceinline__ float fexp(float x) {
    float y = x * 1.44269504f;
    float r = rintf(y);
    float f = y - r;
    float p = 1.3333558e-3f;
    p = fmaf(p, f, 9.6181291e-3f);
    p = fmaf(p, f, 5.5504109e-2f);
    p = fmaf(p, f, 2.4022651e-1f);
    p = fmaf(p, f, 6.9314718e-1f);
    p = fmaf(p, f, 1.0f);
    return __int_as_float(__float_as_int(p) + ((int)r << 23));
}

__device__ __forceinline__ float leaky(float l) {
    return fmaxf(l, 0.f) + 0.2f * fminf(l, 0.f);
}

// -------- Kernel 1: per-node transform + self-loop init --------
// Warp per node. W register-stationary: lane (j = lane&15, half = lane>>4)
// holds W[half*64 .. half*64+63][j] in regs. x read via broadcast LDG.128.
__global__ __launch_bounds__(256) void node_kernel(const float* __restrict__ x,
                                                   const float* __restrict__ W,
                                                   const float* __restrict__ att_src,
                                                   const float* __restrict__ att_dst,
                                                   int N) {
    int lane = threadIdx.x & 31;
    int warp = threadIdx.x >> 5;
    int j = lane & 15, half = lane >> 4;
    int n = blockIdx.x * 8 + warp;
    if (n >= N) return;

    float Wreg[64];
#pragma unroll
    for (int kk = 0; kk < 64; kk++)
        Wreg[kk] = __ldg(&W[(half * 64 + kk) * HC + j]);

    float as_j = __ldg(&att_src[j]);
    float ad_j = __ldg(&att_dst[j]);

    const float4* xp = (const float4*)(x + (size_t)n * IN_F + half * 64);
    float acc = 0.f;
#pragma unroll
    for (int q = 0; q < 16; q++) {
        float4 xv = __ldg(&xp[q]);
        acc = fmaf(xv.x, Wreg[4 * q + 0], acc);
        acc = fmaf(xv.y, Wreg[4 * q + 1], acc);
        acc = fmaf(xv.z, Wreg[4 * q + 2], acc);
        acc = fmaf(xv.w, Wreg[4 * q + 3], acc);
    }
    // combine halves: every lane now has out[j]
    float outj = acc + __shfl_xor_sync(0xffffffffu, acc, 16);

    if (half == 0) g_h[n * HC + j] = outj;

    float vs = outj * as_j, vd = outj * ad_j;
    float asum  = vs + __shfl_xor_sync(0xffffffffu, vs, 1);
    float adsum = vd + __shfl_xor_sync(0xffffffffu, vd, 1);
    float outj1 = __shfl_xor_sync(0xffffffffu, outj, 1);  // even j: out[j+1]

    if (half == 0 && (j & 1) == 0) {
        int hh = j >> 1;
        g_asrc[n * HEADS + hh] = asum;
        g_adst[n * HEADS + hh] = adsum;
        // self-loop contribution (src == dst == n)
        float l = leaky(asum + adsum);
        float p = __expf(l);  // only 800K total, MUFU fine here
        float* accp = g_acc + (size_t)n * 24;
        *(float2*)(accp + j) = make_float2(p * outj, p * outj1);
        accp[16 + hh] = p;
    }
}

// -------- Kernel 2: per-edge gather + fast-exp + scatter (vector red) --------
__global__ __launch_bounds__(256) void edge_kernel(const int* __restrict__ ei, int E) {
    int e = blockIdx.x * blockDim.x + threadIdx.x;
    if (e >= E) return;
    int s = __ldg(&ei[e]);
    int d = __ldg(&ei[E + e]);

    const float4* asp = (const float4*)(g_asrc + (size_t)s * HEADS);
    const float4* adp = (const float4*)(g_adst + (size_t)d * HEADS);
    float4 a0 = asp[0], a1 = asp[1];
    float4 b0 = adp[0], b1 = adp[1];
    float lg[8] = { a0.x + b0.x, a0.y + b0.y, a0.z + b0.z, a0.w + b0.w,
                    a1.x + b1.x, a1.y + b1.y, a1.z + b1.z, a1.w + b1.w };

    const float4* hp = (const float4*)(g_h + (size_t)s * HC);
    float4 h0 = hp[0], h1 = hp[1], h2 = hp[2], h3 = hp[3];
    float hv[16] = { h0.x, h0.y, h0.z, h0.w, h1.x, h1.y, h1.z, h1.w,
                     h2.x, h2.y, h2.z, h2.w, h3.x, h3.y, h3.z, h3.w };

    float S[16], Z[8];
#pragma unroll
    for (int hh = 0; hh < 8; hh++) {
        float p = fexp(leaky(lg[hh]));
        S[2 * hh]     = p * hv[2 * hh];
        S[2 * hh + 1] = p * hv[2 * hh + 1];
        Z[hh] = p;
    }

    float* accp = g_acc + (size_t)d * 24;
#pragma unroll
    for (int q = 0; q < 4; q++) {
        asm volatile("red.global.add.v4.f32 [%0], {%1, %2, %3, %4};"
                     :: "l"(accp + 4 * q), "f"(S[4 * q]), "f"(S[4 * q + 1]),
                        "f"(S[4 * q + 2]), "f"(S[4 * q + 3]) : "memory");
    }
    asm volatile("red.global.add.v4.f32 [%0], {%1, %2, %3, %4};"
                 :: "l"(accp + 16), "f"(Z[0]), "f"(Z[1]), "f"(Z[2]), "f"(Z[3]) : "memory");
    asm volatile("red.global.add.v4.f32 [%0], {%1, %2, %3, %4};"
                 :: "l"(accp + 20), "f"(Z[4]), "f"(Z[5]), "f"(Z[6]), "f"(Z[7]) : "memory");
}

// -------- Kernel 3: normalize + bias + FC --------
__global__ __launch_bounds__(256) void out_kernel(const float* __restrict__ bias_gat,
                                                  const float* __restrict__ W_fc,
                                                  const float* __restrict__ b_fc,
                                                  float* __restrict__ out, int N) {
    int n = blockIdx.x * blockDim.x + threadIdx.x;
    if (n >= N) return;
    const float4* ap = (const float4*)(g_acc + (size_t)n * 24);
    float4 s0 = ap[0], s1 = ap[1], s2 = ap[2], s3 = ap[3];
    float4 z0 = ap[4], z1 = ap[5];
    float S[16] = { s0.x, s0.y, s0.z, s0.w, s1.x, s1.y, s1.z, s1.w,
                    s2.x, s2.y, s2.z, s2.w, s3.x, s3.y, s3.z, s3.w };
    float Z[8]  = { z0.x, z0.y, z0.z, z0.w, z1.x, z1.y, z1.z, z1.w };

    float o0 = __ldg(&b_fc[0]), o1 = __ldg(&b_fc[1]);
#pragma unroll
    for (int hh = 0; hh < 8; hh++) {
        float inv = 1.f / Z[hh];   // Z >= exp(self-loop) > 0 always
        float g0 = S[2 * hh] * inv + __ldg(&bias_gat[2 * hh]);
        float g1 = S[2 * hh + 1] * inv + __ldg(&bias_gat[2 * hh + 1]);
        o0 += g0 * __ldg(&W_fc[(2 * hh) * 2 + 0]) + g1 * __ldg(&W_fc[(2 * hh + 1) * 2 + 0]);
        o1 += g0 * __ldg(&W_fc[(2 * hh) * 2 + 1]) + g1 * __ldg(&W_fc[(2 * hh + 1) * 2 + 1]);
    }
    ((float2*)out)[n] = make_float2(o0, o1);
}

extern "C" void kernel_launch(void* const* d_in, const int* in_sizes, int n_in,
                              void* d_out, int out_size) {
    const float* x        = (const float*)d_in[0];
    const int*   ei       = (const int*)d_in[1];   // int32 (JAX x64 disabled)
    // d_in[2] = edge_attr: unused (GATConv built without edge_dim)
    const float* W        = (const float*)d_in[3];
    const float* att_src  = (const float*)d_in[4];
    const float* att_dst  = (const float*)d_in[5];
    const float* bias_gat = (const float*)d_in[6];
    const float* W_fc     = (const float*)d_in[7];
    const float* b_fc     = (const float*)d_in[8];

    int N = in_sizes[0] / IN_F;
    int E = in_sizes[1] / 2;

    node_kernel<<<(N + 7) / 8, 256>>>(x, W, att_src, att_dst, N);
    edge_kernel<<<(E + 255) / 256, 256>>>(ei, E);
    out_kernel<<<(N + 255) / 256, 256>>>(bias_gat, W_fc, b_fc, (float*)d_out, N);
}

// round 4
// speedup vs baseline: 1.3889x; 1.0445x over previous
#include <cuda_runtime.h>

#define IN_F   128
#define HEADS  8
#define HC     16   // HEADS * OUT_C
#define NMAX   100000
#define NODES_PER_WARP 16

// Static scratch (no allocations allowed)
__device__ __align__(16) float g_h[NMAX * HC];       // transformed features [N,16]
__device__ __align__(16) float g_asrc[NMAX * HEADS]; // alpha_src per node [N,8]
__device__ __align__(16) float g_adst[NMAX * HEADS]; // alpha_dst per node [N,8]
__device__ __align__(16) float g_acc[NMAX * 24];     // per node: S[16] then Z[8]

// FFMA-only exp: exp(x) = 2^(x*log2e); split int/frac, deg-5 Taylor for 2^f,
// exponent injected via integer add on float bits. |x| small here, rel err ~2e-6.
__device__ __forceinline__ float fexp(float x) {
    float y = x * 1.44269504f;
    float r = rintf(y);
    float f = y - r;
    float p = 1.3333558e-3f;
    p = fmaf(p, f, 9.6181291e-3f);
    p = fmaf(p, f, 5.5504109e-2f);
    p = fmaf(p, f, 2.4022651e-1f);
    p = fmaf(p, f, 6.9314718e-1f);
    p = fmaf(p, f, 1.0f);
    return __int_as_float(__float_as_int(p) + ((int)r << 23));
}

__device__ __forceinline__ float leaky(float l) {
    return fmaxf(l, 0.f) + 0.2f * fminf(l, 0.f);
}

// -------- Kernel 1: per-node transform + self-loop init --------
// Warp handles 16 nodes; W register-stationary (amortized). Lane layout:
// j = lane&15 (output column), half = lane>>4 (which 64 of the 128 k's).
__global__ __launch_bounds__(256) void node_kernel(const float* __restrict__ x,
                                                   const float* __restrict__ W,
                                                   const float* __restrict__ att_src,
                                                   const float* __restrict__ att_dst,
                                                   int N) {
    int lane = threadIdx.x & 31;
    int gwarp = blockIdx.x * 8 + (threadIdx.x >> 5);
    int j = lane & 15, half = lane >> 4;
    int n0 = gwarp * NODES_PER_WARP;
    if (n0 >= N) return;

    float Wreg[64];
#pragma unroll
    for (int kk = 0; kk < 64; kk++)
        Wreg[kk] = __ldg(&W[(half * 64 + kk) * HC + j]);

    float as_j = __ldg(&att_src[j]);
    float ad_j = __ldg(&att_dst[j]);

    int nend = min(n0 + NODES_PER_WARP, N);
    for (int n = n0; n < nend; n++) {
        const float4* xp = (const float4*)(x + (size_t)n * IN_F + half * 64);
        float a0 = 0.f, a1 = 0.f, a2 = 0.f, a3 = 0.f;
#pragma unroll
        for (int q = 0; q < 4; q++) {
            float4 v0 = __ldg(&xp[4 * q + 0]);
            float4 v1 = __ldg(&xp[4 * q + 1]);
            float4 v2 = __ldg(&xp[4 * q + 2]);
            float4 v3 = __ldg(&xp[4 * q + 3]);
            a0 = fmaf(v0.x, Wreg[16 * q + 0], a0);
            a0 = fmaf(v0.y, Wreg[16 * q + 1], a0);
            a0 = fmaf(v0.z, Wreg[16 * q + 2], a0);
            a0 = fmaf(v0.w, Wreg[16 * q + 3], a0);
            a1 = fmaf(v1.x, Wreg[16 * q + 4], a1);
            a1 = fmaf(v1.y, Wreg[16 * q + 5], a1);
            a1 = fmaf(v1.z, Wreg[16 * q + 6], a1);
            a1 = fmaf(v1.w, Wreg[16 * q + 7], a1);
            a2 = fmaf(v2.x, Wreg[16 * q + 8], a2);
            a2 = fmaf(v2.y, Wreg[16 * q + 9], a2);
            a2 = fmaf(v2.z, Wreg[16 * q + 10], a2);
            a2 = fmaf(v2.w, Wreg[16 * q + 11], a2);
            a3 = fmaf(v3.x, Wreg[16 * q + 12], a3);
            a3 = fmaf(v3.y, Wreg[16 * q + 13], a3);
            a3 = fmaf(v3.z, Wreg[16 * q + 14], a3);
            a3 = fmaf(v3.w, Wreg[16 * q + 15], a3);
        }
        float acc = (a0 + a1) + (a2 + a3);
        // combine halves: every lane gets out[j]
        float outj = acc + __shfl_xor_sync(0xffffffffu, acc, 16);

        float vs = outj * as_j, vd = outj * ad_j;
        float asum  = vs + __shfl_xor_sync(0xffffffffu, vs, 1);
        float adsum = vd + __shfl_xor_sync(0xffffffffu, vd, 1);
        float outj1 = __shfl_xor_sync(0xffffffffu, outj, 1);  // even j: out[j+1]

        if (half == 0 && (j & 1) == 0) {
            int hh = j >> 1;
            *(float2*)(g_h + (size_t)n * HC + j) = make_float2(outj, outj1);
            g_asrc[n * HEADS + hh] = asum;
            g_adst[n * HEADS + hh] = adsum;
            // self-loop contribution (src == dst == n)
            float p = fexp(leaky(asum + adsum));
            float* accp = g_acc + (size_t)n * 24;
            *(float2*)(accp + j) = make_float2(p * outj, p * outj1);
            accp[16 + hh] = p;
        }
    }
}

// -------- Kernel 2: per-edge gather + fast-exp + scatter (vector red) --------
__global__ __launch_bounds__(256) void edge_kernel(const int* __restrict__ ei, int E) {
    int e = blockIdx.x * blockDim.x + threadIdx.x;
    if (e >= E) return;
    int s = __ldg(&ei[e]);
    int d = __ldg(&ei[E + e]);

    const float4* asp = (const float4*)(g_asrc + (size_t)s * HEADS);
    const float4* adp = (const float4*)(g_adst + (size_t)d * HEADS);
    float4 a0 = asp[0], a1 = asp[1];
    float4 b0 = adp[0], b1 = adp[1];
    float lg[8] = { a0.x + b0.x, a0.y + b0.y, a0.z + b0.z, a0.w + b0.w,
                    a1.x + b1.x, a1.y + b1.y, a1.z + b1.z, a1.w + b1.w };

    const float4* hp = (const float4*)(g_h + (size_t)s * HC);
    float4 h0 = hp[0], h1 = hp[1], h2 = hp[2], h3 = hp[3];
    float hv[16] = { h0.x, h0.y, h0.z, h0.w, h1.x, h1.y, h1.z, h1.w,
                     h2.x, h2.y, h2.z, h2.w, h3.x, h3.y, h3.z, h3.w };

    float S[16], Z[8];
#pragma unroll
    for (int hh = 0; hh < 8; hh++) {
        float p = fexp(leaky(lg[hh]));
        S[2 * hh]     = p * hv[2 * hh];
        S[2 * hh + 1] = p * hv[2 * hh + 1];
        Z[hh] = p;
    }

    float* accp = g_acc + (size_t)d * 24;
#pragma unroll
    for (int q = 0; q < 4; q++) {
        asm volatile("red.global.add.v4.f32 [%0], {%1, %2, %3, %4};"
                     :: "l"(accp + 4 * q), "f"(S[4 * q]), "f"(S[4 * q + 1]),
                        "f"(S[4 * q + 2]), "f"(S[4 * q + 3]) : "memory");
    }
    asm volatile("red.global.add.v4.f32 [%0], {%1, %2, %3, %4};"
                 :: "l"(accp + 16), "f"(Z[0]), "f"(Z[1]), "f"(Z[2]), "f"(Z[3]) : "memory");
    asm volatile("red.global.add.v4.f32 [%0], {%1, %2, %3, %4};"
                 :: "l"(accp + 20), "f"(Z[4]), "f"(Z[5]), "f"(Z[6]), "f"(Z[7]) : "memory");
}

// -------- Kernel 3: normalize + bias + FC --------
__global__ __launch_bounds__(256) void out_kernel(const float* __restrict__ bias_gat,
                                                  const float* __restrict__ W_fc,
                                                  const float* __restrict__ b_fc,
                                                  float* __restrict__ out, int N) {
    int n = blockIdx.x * blockDim.x + threadIdx.x;
    if (n >= N) return;
    const float4* ap = (const float4*)(g_acc + (size_t)n * 24);
    float4 s0 = ap[0], s1 = ap[1], s2 = ap[2], s3 = ap[3];
    float4 z0 = ap[4], z1 = ap[5];
    float S[16] = { s0.x, s0.y, s0.z, s0.w, s1.x, s1.y, s1.z, s1.w,
                    s2.x, s2.y, s2.z, s2.w, s3.x, s3.y, s3.z, s3.w };
    float Z[8]  = { z0.x, z0.y, z0.z, z0.w, z1.x, z1.y, z1.z, z1.w };

    float o0 = __ldg(&b_fc[0]), o1 = __ldg(&b_fc[1]);
#pragma unroll
    for (int hh = 0; hh < 8; hh++) {
        float inv = 1.f / Z[hh];   // Z >= exp(self-loop) > 0 always
        float g0 = S[2 * hh] * inv + __ldg(&bias_gat[2 * hh]);
        float g1 = S[2 * hh + 1] * inv + __ldg(&bias_gat[2 * hh + 1]);
        o0 += g0 * __ldg(&W_fc[(2 * hh) * 2 + 0]) + g1 * __ldg(&W_fc[(2 * hh + 1) * 2 + 0]);
        o1 += g0 * __ldg(&W_fc[(2 * hh) * 2 + 1]) + g1 * __ldg(&W_fc[(2 * hh + 1) * 2 + 1]);
    }
    ((float2*)out)[n] = make_float2(o0, o1);
}

extern "C" void kernel_launch(void* const* d_in, const int* in_sizes, int n_in,
                              void* d_out, int out_size) {
    const float* x        = (const float*)d_in[0];
    const int*   ei       = (const int*)d_in[1];   // int32 (JAX x64 disabled)
    // d_in[2] = edge_attr: unused (GATConv built without edge_dim)
    const float* W        = (const float*)d_in[3];
    const float* att_src  = (const float*)d_in[4];
    const float* att_dst  = (const float*)d_in[5];
    const float* bias_gat = (const float*)d_in[6];
    const float* W_fc     = (const float*)d_in[7];
    const float* b_fc     = (const float*)d_in[8];

    int N = in_sizes[0] / IN_F;
    int E = in_sizes[1] / 2;

    int warps = (N + NODES_PER_WARP - 1) / NODES_PER_WARP;
    node_kernel<<<(warps + 7) / 8, 256>>>(x, W, att_src, att_dst, N);
    edge_kernel<<<(E + 255) / 256, 256>>>(ei, E);
    out_kernel<<<(N + 255) / 256, 256>>>(bias_gat, W_fc, b_fc, (float*)d_out, N);
}

// round 5
// speedup vs baseline: 2.0321x; 1.4631x over previous
#include <cuda_runtime.h>

#define IN_F   128
#define HEADS  8
#define HC     16   // HEADS * OUT_C
#define NMAX   100000
#define TILE   64    // nodes per CTA in node_kernel

// Static scratch (no allocations allowed)
__device__ __align__(16) float g_h[NMAX * HC];       // transformed features [N,16]
__device__ __align__(16) float g_asrc[NMAX * HEADS]; // alpha_src per node [N,8]
__device__ __align__(16) float g_adst[NMAX * HEADS]; // alpha_dst per node [N,8]
__device__ __align__(16) float g_acc[NMAX * 24];     // per node: S[16] then Z[8]

// FFMA-only exp: exp(x) = 2^(x*log2e); split int/frac, deg-5 poly for 2^f,
// exponent injected via integer add on float bits. |x| small here, rel err ~2e-6.
__device__ __forceinline__ float fexp(float x) {
    float y = x * 1.44269504f;
    float r = rintf(y);
    float f = y - r;
    float p = 1.3333558e-3f;
    p = fmaf(p, f, 9.6181291e-3f);
    p = fmaf(p, f, 5.5504109e-2f);
    p = fmaf(p, f, 2.4022651e-1f);
    p = fmaf(p, f, 6.9314718e-1f);
    p = fmaf(p, f, 1.0f);
    return __int_as_float(__float_as_int(p) + ((int)r << 23));
}

__device__ __forceinline__ float leaky(float l) {
    return fmaxf(l, 0.f) + 0.2f * fminf(l, 0.f);
}

// -------- Kernel 1: per-node transform + self-loop init --------
// CTA stages TILE=64 x-rows into smem with coalesced LDG.128, then each of the
// 8 warps computes 8 nodes with W register-stationary and broadcast LDS reads.
__global__ __launch_bounds__(256, 2) void node_kernel(const float* __restrict__ x,
                                                      const float* __restrict__ W,
                                                      const float* __restrict__ att_src,
                                                      const float* __restrict__ att_dst,
                                                      int N) {
    __shared__ __align__(16) float xs[TILE * IN_F];   // 32KB
    int tid = threadIdx.x;
    int lane = tid & 31;
    int warp = tid >> 5;
    int j = lane & 15, half = lane >> 4;
    int n0 = blockIdx.x * TILE;
    if (n0 >= N) return;

    // W register-stationary: lane holds W[half*64+kk][j]
    float Wreg[64];
#pragma unroll
    for (int kk = 0; kk < 64; kk++)
        Wreg[kk] = __ldg(&W[(half * 64 + kk) * HC + j]);
    float as_j = __ldg(&att_src[j]);
    float ad_j = __ldg(&att_dst[j]);

    // Stage tile (coalesced). 2048 float4 / 256 threads = 8 each.
    {
        const float4* xg = (const float4*)(x + (size_t)n0 * IN_F);
        float4* xsv = (float4*)xs;
        int nvec = (min(TILE, N - n0)) * (IN_F / 4);
#pragma unroll
        for (int q = 0; q < TILE * IN_F / 4 / 256; q++) {
            int idx = q * 256 + tid;
            if (idx < nvec) xsv[idx] = xg[idx];
        }
    }
    __syncthreads();

    int cnt = min(TILE, N - n0);
    for (int i = warp; i < cnt; i += 8) {
        int n = n0 + i;
        const float4* xp = (const float4*)(xs + i * IN_F + half * 64);
        float a0 = 0.f, a1 = 0.f, a2 = 0.f, a3 = 0.f;
#pragma unroll
        for (int q = 0; q < 4; q++) {
            float4 v0 = xp[4 * q + 0];
            float4 v1 = xp[4 * q + 1];
            float4 v2 = xp[4 * q + 2];
            float4 v3 = xp[4 * q + 3];
            a0 = fmaf(v0.x, Wreg[16 * q + 0], a0);
            a0 = fmaf(v0.y, Wreg[16 * q + 1], a0);
            a0 = fmaf(v0.z, Wreg[16 * q + 2], a0);
            a0 = fmaf(v0.w, Wreg[16 * q + 3], a0);
            a1 = fmaf(v1.x, Wreg[16 * q + 4], a1);
            a1 = fmaf(v1.y, Wreg[16 * q + 5], a1);
            a1 = fmaf(v1.z, Wreg[16 * q + 6], a1);
            a1 = fmaf(v1.w, Wreg[16 * q + 7], a1);
            a2 = fmaf(v2.x, Wreg[16 * q + 8], a2);
            a2 = fmaf(v2.y, Wreg[16 * q + 9], a2);
            a2 = fmaf(v2.z, Wreg[16 * q + 10], a2);
            a2 = fmaf(v2.w, Wreg[16 * q + 11], a2);
            a3 = fmaf(v3.x, Wreg[16 * q + 12], a3);
            a3 = fmaf(v3.y, Wreg[16 * q + 13], a3);
            a3 = fmaf(v3.z, Wreg[16 * q + 14], a3);
            a3 = fmaf(v3.w, Wreg[16 * q + 15], a3);
        }
        float acc = (a0 + a1) + (a2 + a3);
        float outj = acc + __shfl_xor_sync(0xffffffffu, acc, 16);

        float vs = outj * as_j, vd = outj * ad_j;
        float asum  = vs + __shfl_xor_sync(0xffffffffu, vs, 1);
        float adsum = vd + __shfl_xor_sync(0xffffffffu, vd, 1);
        float outj1 = __shfl_xor_sync(0xffffffffu, outj, 1);  // even j: out[j+1]

        if (half == 0 && (j & 1) == 0) {
            int hh = j >> 1;
            *(float2*)(g_h + (size_t)n * HC + j) = make_float2(outj, outj1);
            g_asrc[n * HEADS + hh] = asum;
            g_adst[n * HEADS + hh] = adsum;
            // self-loop contribution (src == dst == n)
            float p = fexp(leaky(asum + adsum));
            float* accp = g_acc + (size_t)n * 24;
            *(float2*)(accp + j) = make_float2(p * outj, p * outj1);
            accp[16 + hh] = p;
        }
    }
}

// -------- Kernel 2: per-edge gather + fast-exp + scatter (vector red) --------
// Two threads per edge: thread q in {0,1} handles heads 4q..4q+3.
__global__ __launch_bounds__(256) void edge_kernel(const int* __restrict__ ei, int E) {
    int t = blockIdx.x * blockDim.x + threadIdx.x;
    int e = t >> 1;
    if (e >= E) return;
    int q = t & 1;
    int s = __ldg(&ei[e]);
    int d = __ldg(&ei[E + e]);

    float4 a = *(const float4*)(g_asrc + (size_t)s * HEADS + 4 * q);
    float4 b = *(const float4*)(g_adst + (size_t)d * HEADS + 4 * q);
    float lg[4] = { a.x + b.x, a.y + b.y, a.z + b.z, a.w + b.w };

    const float4* hp = (const float4*)(g_h + (size_t)s * HC + 8 * q);
    float4 h0 = hp[0], h1 = hp[1];
    float hv[8] = { h0.x, h0.y, h0.z, h0.w, h1.x, h1.y, h1.z, h1.w };

    float S[8], Z[4];
#pragma unroll
    for (int hh = 0; hh < 4; hh++) {
        float p = fexp(leaky(lg[hh]));
        S[2 * hh]     = p * hv[2 * hh];
        S[2 * hh + 1] = p * hv[2 * hh + 1];
        Z[hh] = p;
    }

    float* accp = g_acc + (size_t)d * 24;
    asm volatile("red.global.add.v4.f32 [%0], {%1, %2, %3, %4};"
                 :: "l"(accp + 8 * q), "f"(S[0]), "f"(S[1]), "f"(S[2]), "f"(S[3]) : "memory");
    asm volatile("red.global.add.v4.f32 [%0], {%1, %2, %3, %4};"
                 :: "l"(accp + 8 * q + 4), "f"(S[4]), "f"(S[5]), "f"(S[6]), "f"(S[7]) : "memory");
    asm volatile("red.global.add.v4.f32 [%0], {%1, %2, %3, %4};"
                 :: "l"(accp + 16 + 4 * q), "f"(Z[0]), "f"(Z[1]), "f"(Z[2]), "f"(Z[3]) : "memory");
}

// -------- Kernel 3: normalize + bias + FC --------
__global__ __launch_bounds__(256) void out_kernel(const float* __restrict__ bias_gat,
                                                  const float* __restrict__ W_fc,
                                                  const float* __restrict__ b_fc,
                                                  float* __restrict__ out, int N) {
    int n = blockIdx.x * blockDim.x + threadIdx.x;
    if (n >= N) return;
    const float4* ap = (const float4*)(g_acc + (size_t)n * 24);
    float4 s0 = ap[0], s1 = ap[1], s2 = ap[2], s3 = ap[3];
    float4 z0 = ap[4], z1 = ap[5];
    float S[16] = { s0.x, s0.y, s0.z, s0.w, s1.x, s1.y, s1.z, s1.w,
                    s2.x, s2.y, s2.z, s2.w, s3.x, s3.y, s3.z, s3.w };
    float Z[8]  = { z0.x, z0.y, z0.z, z0.w, z1.x, z1.y, z1.z, z1.w };

    float o0 = __ldg(&b_fc[0]), o1 = __ldg(&b_fc[1]);
#pragma unroll
    for (int hh = 0; hh < 8; hh++) {
        float inv = 1.f / Z[hh];   // Z >= exp(self-loop) > 0 always
        float g0 = S[2 * hh] * inv + __ldg(&bias_gat[2 * hh]);
        float g1 = S[2 * hh + 1] * inv + __ldg(&bias_gat[2 * hh + 1]);
        o0 += g0 * __ldg(&W_fc[(2 * hh) * 2 + 0]) + g1 * __ldg(&W_fc[(2 * hh + 1) * 2 + 0]);
        o1 += g0 * __ldg(&W_fc[(2 * hh) * 2 + 1]) + g1 * __ldg(&W_fc[(2 * hh + 1) * 2 + 1]);
    }
    ((float2*)out)[n] = make_float2(o0, o1);
}

extern "C" void kernel_launch(void* const* d_in, const int* in_sizes, int n_in,
                              void* d_out, int out_size) {
    const float* x        = (const float*)d_in[0];
    const int*   ei       = (const int*)d_in[1];   // int32 (JAX x64 disabled)
    // d_in[2] = edge_attr: unused (GATConv built without edge_dim)
    const float* W        = (const float*)d_in[3];
    const float* att_src  = (const float*)d_in[4];
    const float* att_dst  = (const float*)d_in[5];
    const float* bias_gat = (const float*)d_in[6];
    const float* W_fc     = (const float*)d_in[7];
    const float* b_fc     = (const float*)d_in[8];

    int N = in_sizes[0] / IN_F;
    int E = in_sizes[1] / 2;

    node_kernel<<<(N + TILE - 1) / TILE, 256>>>(x, W, att_src, att_dst, N);
    long long tthreads = 2LL * E;
    edge_kernel<<<(int)((tthreads + 255) / 256), 256>>>(ei, E);
    out_kernel<<<(N + 255) / 256, 256>>>(bias_gat, W_fc, b_fc, (float*)d_out, N);
}

// round 7
// speedup vs baseline: 2.1922x; 1.0788x over previous
#include <cuda_runtime.h>
#include <cuda_fp16.h>

#define IN_F   128
#define HEADS  8
#define HC     16   // HEADS * OUT_C
#define NMAX   100000
#define TILE   64    // nodes per CTA in node_kernel

// Static scratch (no allocations allowed)
__device__ __align__(32) __half2 g_hh[NMAX * 8];     // h in fp16: 32B per node
__device__ __align__(16) float g_asrc[NMAX * HEADS]; // alpha_src per node [N,8]
__device__ __align__(16) float g_adst[NMAX * HEADS]; // alpha_dst per node [N,8]
__device__ __align__(16) float g_acc[NMAX * 24];     // per node: S[16] then Z[8]

// FFMA-only exp: exp(x) = 2^(x*log2e); split int/frac, deg-5 poly for 2^f,
// exponent injected via integer add on float bits. |x| small here, rel err ~2e-6.
__device__ __forceinline__ float fexp(float x) {
    float y = x * 1.44269504f;
    float r = rintf(y);
    float f = y - r;
    float p = 1.3333558e-3f;
    p = fmaf(p, f, 9.6181291e-3f);
    p = fmaf(p, f, 5.5504109e-2f);
    p = fmaf(p, f, 2.4022651e-1f);
    p = fmaf(p, f, 6.9314718e-1f);
    p = fmaf(p, f, 1.0f);
    return __int_as_float(__float_as_int(p) + ((int)r << 23));
}

__device__ __forceinline__ float leaky(float l) {
    return fmaxf(l, 0.f) + 0.2f * fminf(l, 0.f);
}

// -------- Kernel 1: per-node transform + self-loop init --------
// CTA stages TILE=64 x-rows into smem with coalesced LDG.128, then each of the
// 8 warps computes 8 nodes with W register-stationary and broadcast LDS reads.
__global__ __launch_bounds__(256, 2) void node_kernel(const float* __restrict__ x,
                                                      const float* __restrict__ W,
                                                      const float* __restrict__ att_src,
                                                      const float* __restrict__ att_dst,
                                                      int N) {
    __shared__ __align__(16) float xs[TILE * IN_F];   // 32KB
    int tid = threadIdx.x;
    int lane = tid & 31;
    int warp = tid >> 5;
    int j = lane & 15, half = lane >> 4;
    int n0 = blockIdx.x * TILE;
    if (n0 >= N) return;

    // W register-stationary: lane holds W[half*64+kk][j]
    float Wreg[64];
#pragma unroll
    for (int kk = 0; kk < 64; kk++)
        Wreg[kk] = __ldg(&W[(half * 64 + kk) * HC + j]);
    float as_j = __ldg(&att_src[j]);
    float ad_j = __ldg(&att_dst[j]);

    // Stage tile (coalesced). 2048 float4 / 256 threads = 8 each.
    {
        const float4* xg = (const float4*)(x + (size_t)n0 * IN_F);
        float4* xsv = (float4*)xs;
        int nvec = (min(TILE, N - n0)) * (IN_F / 4);
#pragma unroll
        for (int q = 0; q < TILE * IN_F / 4 / 256; q++) {
            int idx = q * 256 + tid;
            if (idx < nvec) xsv[idx] = xg[idx];
        }
    }
    __syncthreads();

    int cnt = min(TILE, N - n0);
    for (int i = warp; i < cnt; i += 8) {
        int n = n0 + i;
        const float4* xp = (const float4*)(xs + i * IN_F + half * 64);
        float a0 = 0.f, a1 = 0.f, a2 = 0.f, a3 = 0.f;
#pragma unroll
        for (int q = 0; q < 4; q++) {
            float4 v0 = xp[4 * q + 0];
            float4 v1 = xp[4 * q + 1];
            float4 v2 = xp[4 * q + 2];
            float4 v3 = xp[4 * q + 3];
            a0 = fmaf(v0.x, Wreg[16 * q + 0], a0);
            a0 = fmaf(v0.y, Wreg[16 * q + 1], a0);
            a0 = fmaf(v0.z, Wreg[16 * q + 2], a0);
            a0 = fmaf(v0.w, Wreg[16 * q + 3], a0);
            a1 = fmaf(v1.x, Wreg[16 * q + 4], a1);
            a1 = fmaf(v1.y, Wreg[16 * q + 5], a1);
            a1 = fmaf(v1.z, Wreg[16 * q + 6], a1);
            a1 = fmaf(v1.w, Wreg[16 * q + 7], a1);
            a2 = fmaf(v2.x, Wreg[16 * q + 8], a2);
            a2 = fmaf(v2.y, Wreg[16 * q + 9], a2);
            a2 = fmaf(v2.z, Wreg[16 * q + 10], a2);
            a2 = fmaf(v2.w, Wreg[16 * q + 11], a2);
            a3 = fmaf(v3.x, Wreg[16 * q + 12], a3);
            a3 = fmaf(v3.y, Wreg[16 * q + 13], a3);
            a3 = fmaf(v3.z, Wreg[16 * q + 14], a3);
            a3 = fmaf(v3.w, Wreg[16 * q + 15], a3);
        }
        float acc = (a0 + a1) + (a2 + a3);
        float outj = acc + __shfl_xor_sync(0xffffffffu, acc, 16);

        float vs = outj * as_j, vd = outj * ad_j;
        float asum  = vs + __shfl_xor_sync(0xffffffffu, vs, 1);
        float adsum = vd + __shfl_xor_sync(0xffffffffu, vd, 1);
        float outj1 = __shfl_xor_sync(0xffffffffu, outj, 1);  // even j: out[j+1]

        if (half == 0 && (j & 1) == 0) {
            int hh = j >> 1;
            // half2 index for value pair (j, j+1) is j/2 == hh
            g_hh[(size_t)n * 8 + hh] = __floats2half2_rn(outj, outj1);
            g_asrc[n * HEADS + hh] = asum;
            g_adst[n * HEADS + hh] = adsum;
            // self-loop contribution (src == dst == n) in fp32
            float p = fexp(leaky(asum + adsum));
            float* accp = g_acc + (size_t)n * 24;
            *(float2*)(accp + j) = make_float2(p * outj, p * outj1);
            accp[16 + hh] = p;
        }
    }
}

// -------- Kernel 2: per-edge gather + fast-exp + scatter (vector red) --------
// Four threads per edge: thread q in {0..3} handles heads 2q, 2q+1.
__global__ __launch_bounds__(256) void edge_kernel(const int* __restrict__ ei, int E) {
    int t = blockIdx.x * blockDim.x + threadIdx.x;
    int e = t >> 2;
    if (e >= E) return;
    int q = t & 3;
    int s = __ldg(&ei[e]);
    int d = __ldg(&ei[E + e]);

    float2 a = *(const float2*)(g_asrc + (size_t)s * HEADS + 2 * q);
    float2 b = *(const float2*)(g_adst + (size_t)d * HEADS + 2 * q);
    float p0 = fexp(leaky(a.x + b.x));
    float p1 = fexp(leaky(a.y + b.y));

    // heads 2q, 2q+1 -> values 4q..4q+3 -> half2 indices 2q, 2q+1
    uint2 hraw = *(const uint2*)(g_hh + (size_t)s * 8 + 2 * q);
    float2 f01 = __half22float2(*(__half2*)&hraw.x);  // h[4q], h[4q+1]
    float2 f23 = __half22float2(*(__half2*)&hraw.y);  // h[4q+2], h[4q+3]

    float* accp = g_acc + (size_t)d * 24;
    asm volatile("red.global.add.v4.f32 [%0], {%1, %2, %3, %4};"
                 :: "l"(accp + 4 * q),
                    "f"(p0 * f01.x), "f"(p0 * f01.y),
                    "f"(p1 * f23.x), "f"(p1 * f23.y) : "memory");

    // Z: pair threads (q, q^1); even-q thread issues v4 with own+partner p's.
    float pp0 = __shfl_xor_sync(0xffffffffu, p0, 1);
    float pp1 = __shfl_xor_sync(0xffffffffu, p1, 1);
    if ((q & 1) == 0) {
        asm volatile("red.global.add.v4.f32 [%0], {%1, %2, %3, %4};"
                     :: "l"(accp + 16 + 2 * q),
                        "f"(p0), "f"(p1), "f"(pp0), "f"(pp1) : "memory");
    }
}

// -------- Kernel 3: normalize + bias + FC --------
__global__ __launch_bounds__(256) void out_kernel(const float* __restrict__ bias_gat,
                                                  const float* __restrict__ W_fc,
                                                  const float* __restrict__ b_fc,
                                                  float* __restrict__ out, int N) {
    int n = blockIdx.x * blockDim.x + threadIdx.x;
    if (n >= N) return;
    const float4* ap = (const float4*)(g_acc + (size_t)n * 24);
    float4 s0 = ap[0], s1 = ap[1], s2 = ap[2], s3 = ap[3];
    float4 z0 = ap[4], z1 = ap[5];
    float S[16] = { s0.x, s0.y, s0.z, s0.w, s1.x, s1.y, s1.z, s1.w,
                    s2.x, s2.y, s2.z, s2.w, s3.x, s3.y, s3.z, s3.w };
    float Z[8]  = { z0.x, z0.y, z0.z, z0.w, z1.x, z1.y, z1.z, z1.w };

    float o0 = __ldg(&b_fc[0]), o1 = __ldg(&b_fc[1]);
#pragma unroll
    for (int hh = 0; hh < 8; hh++) {
        float inv = 1.f / Z[hh];   // Z >= exp(self-loop) > 0 always
        float g0 = S[2 * hh] * inv + __ldg(&bias_gat[2 * hh]);
        float g1 = S[2 * hh + 1] * inv + __ldg(&bias_gat[2 * hh + 1]);
        o0 += g0 * __ldg(&W_fc[(2 * hh) * 2 + 0]) + g1 * __ldg(&W_fc[(2 * hh + 1) * 2 + 0]);
        o1 += g0 * __ldg(&W_fc[(2 * hh) * 2 + 1]) + g1 * __ldg(&W_fc[(2 * hh + 1) * 2 + 1]);
    }
    ((float2*)out)[n] = make_float2(o0, o1);
}

extern "C" void kernel_launch(void* const* d_in, const int* in_sizes, int n_in,
                              void* d_out, int out_size) {
    const float* x        = (const float*)d_in[0];
    const int*   ei       = (const int*)d_in[1];   // int32 (JAX x64 disabled)
    // d_in[2] = edge_attr: unused (GATConv built without edge_dim)
    const float* W        = (const float*)d_in[3];
    const float* att_src  = (const float*)d_in[4];
    const float* att_dst  = (const float*)d_in[5];
    const float* bias_gat = (const float*)d_in[6];
    const float* W_fc     = (const float*)d_in[7];
    const float* b_fc     = (const float*)d_in[8];

    int N = in_sizes[0] / IN_F;
    int E = in_sizes[1] / 2;

    node_kernel<<<(N + TILE - 1) / TILE, 256>>>(x, W, att_src, att_dst, N);
    long long tthreads = 4LL * E;
    edge_kernel<<<(int)((tthreads + 255) / 256), 256>>>(ei, E);
    out_kernel<<<(N + 255) / 256, 256>>>(bias_gat, W_fc, b_fc, (float*)d_out, N);
}

// round 8
// speedup vs baseline: 2.3014x; 1.0498x over previous
#include <cuda_runtime.h>
#include <cuda_fp16.h>

#define IN_F   128
#define HEADS  8
#define HC     16   // HEADS * OUT_C
#define NMAX   100000
#define NT     256   // threads (=nodes) per CTA in node_kernel
#define KT     32    // k-tile width
#define XPAD   36    // padded row stride (floats): conflict-free + 16B aligned

// Static scratch (no allocations allowed)
__device__ __align__(32) __half2 g_hh[NMAX * 8];     // h in fp16: 32B per node
__device__ __align__(16) float g_asrc[NMAX * HEADS]; // alpha_src per node [N,8]
__device__ __align__(16) float g_adst[NMAX * HEADS]; // alpha_dst per node [N,8]
__device__ __align__(16) float g_acc[NMAX * 24];     // per node: S[16] then Z[8]

// FFMA-only exp: exp(x) = 2^(x*log2e); split int/frac, deg-5 poly for 2^f,
// exponent injected via integer add on float bits. |x| small here, rel err ~2e-6.
__device__ __forceinline__ float fexp(float x) {
    float y = x * 1.44269504f;
    float r = rintf(y);
    float f = y - r;
    float p = 1.3333558e-3f;
    p = fmaf(p, f, 9.6181291e-3f);
    p = fmaf(p, f, 5.5504109e-2f);
    p = fmaf(p, f, 2.4022651e-1f);
    p = fmaf(p, f, 6.9314718e-1f);
    p = fmaf(p, f, 1.0f);
    return __int_as_float(__float_as_int(p) + ((int)r << 23));
}

__device__ __forceinline__ float leaky(float l) {
    return fmaxf(l, 0.f) + 0.2f * fminf(l, 0.f);
}

// -------- Kernel 1: per-node transform + self-loop init --------
// Thread per node. W (8KB) in smem, read via broadcast LDS.128. x staged in
// 32-column tiles with padded stride (conflict-free). acc[16] per thread; no
// cross-lane ops. Tail writes h(fp16), a_src/a_dst, self-loop acc init.
__global__ __launch_bounds__(NT) void node_kernel(const float* __restrict__ x,
                                                  const float* __restrict__ W,
                                                  const float* __restrict__ att_src,
                                                  const float* __restrict__ att_dst,
                                                  int N) {
    __shared__ __align__(16) float Ws[IN_F * HC];   // 8KB, Ws[k*16+j] == W layout
    __shared__ __align__(16) float xs[NT * XPAD];   // 36.9KB
    __shared__ float s_att[2 * HC];                 // att_src[16], att_dst[16]

    int tid = threadIdx.x;
    int n0 = blockIdx.x * NT;
    int n = n0 + tid;

    // Copy W (same layout) coalesced as float4
    {
        const float4* Wg = (const float4*)W;
        float4* Wsv = (float4*)Ws;
        for (int i = tid; i < IN_F * HC / 4; i += NT) Wsv[i] = Wg[i];
    }
    if (tid < HC) { s_att[tid] = att_src[tid]; s_att[HC + tid] = att_dst[tid]; }

    float acc[HC];
#pragma unroll
    for (int j = 0; j < HC; j++) acc[j] = 0.f;

#pragma unroll 1
    for (int kt = 0; kt < IN_F / KT; kt++) {
        __syncthreads();
        // Stage x[:, kt*32 .. kt*32+31] for NT rows: 2048 float4, coalesced.
        {
#pragma unroll
            for (int q = 0; q < NT * KT / 4 / NT; q++) {   // 8 iters
                int idx = q * NT + tid;
                int r = idx >> 3, c = idx & 7;
                if (n0 + r < N) {
                    float4 v = *(const float4*)(x + (size_t)(n0 + r) * IN_F + kt * KT + c * 4);
                    *(float4*)&xs[r * XPAD + c * 4] = v;
                }
            }
        }
        __syncthreads();
        if (n < N) {
#pragma unroll
            for (int q = 0; q < KT / 4; q++) {   // 8 float4 of x per tile
                float4 xv = *(const float4*)&xs[tid * XPAD + 4 * q];
                int kb = kt * KT + 4 * q;
                const float4* wr = (const float4*)&Ws[kb * HC];
#pragma unroll
                for (int kk = 0; kk < 4; kk++) {
                    float xk = (kk == 0) ? xv.x : (kk == 1) ? xv.y : (kk == 2) ? xv.z : xv.w;
                    float4 w0 = wr[kk * 4 + 0];
                    float4 w1 = wr[kk * 4 + 1];
                    float4 w2 = wr[kk * 4 + 2];
                    float4 w3 = wr[kk * 4 + 3];
                    acc[0]  = fmaf(xk, w0.x, acc[0]);
                    acc[1]  = fmaf(xk, w0.y, acc[1]);
                    acc[2]  = fmaf(xk, w0.z, acc[2]);
                    acc[3]  = fmaf(xk, w0.w, acc[3]);
                    acc[4]  = fmaf(xk, w1.x, acc[4]);
                    acc[5]  = fmaf(xk, w1.y, acc[5]);
                    acc[6]  = fmaf(xk, w1.z, acc[6]);
                    acc[7]  = fmaf(xk, w1.w, acc[7]);
                    acc[8]  = fmaf(xk, w2.x, acc[8]);
                    acc[9]  = fmaf(xk, w2.y, acc[9]);
                    acc[10] = fmaf(xk, w2.z, acc[10]);
                    acc[11] = fmaf(xk, w2.w, acc[11]);
                    acc[12] = fmaf(xk, w3.x, acc[12]);
                    acc[13] = fmaf(xk, w3.y, acc[13]);
                    acc[14] = fmaf(xk, w3.z, acc[14]);
                    acc[15] = fmaf(xk, w3.w, acc[15]);
                }
            }
        }
    }

    if (n >= N) return;

    // h in fp16 (32B row)
    {
        uint4 u0, u1;
        __half2 t;
        t = __floats2half2_rn(acc[0],  acc[1]);  u0.x = *(unsigned*)&t;
        t = __floats2half2_rn(acc[2],  acc[3]);  u0.y = *(unsigned*)&t;
        t = __floats2half2_rn(acc[4],  acc[5]);  u0.z = *(unsigned*)&t;
        t = __floats2half2_rn(acc[6],  acc[7]);  u0.w = *(unsigned*)&t;
        t = __floats2half2_rn(acc[8],  acc[9]);  u1.x = *(unsigned*)&t;
        t = __floats2half2_rn(acc[10], acc[11]); u1.y = *(unsigned*)&t;
        t = __floats2half2_rn(acc[12], acc[13]); u1.z = *(unsigned*)&t;
        t = __floats2half2_rn(acc[14], acc[15]); u1.w = *(unsigned*)&t;
        *(uint4*)(g_hh + (size_t)n * 8)     = u0;
        *(uint4*)(g_hh + (size_t)n * 8 + 4) = u1;
    }

    // attention dots + self-loop init
    float as[HEADS], ad[HEADS];
#pragma unroll
    for (int hh = 0; hh < HEADS; hh++) {
        as[hh] = acc[2 * hh] * s_att[2 * hh] + acc[2 * hh + 1] * s_att[2 * hh + 1];
        ad[hh] = acc[2 * hh] * s_att[HC + 2 * hh] + acc[2 * hh + 1] * s_att[HC + 2 * hh + 1];
    }
    *(float4*)(g_asrc + (size_t)n * HEADS)     = make_float4(as[0], as[1], as[2], as[3]);
    *(float4*)(g_asrc + (size_t)n * HEADS + 4) = make_float4(as[4], as[5], as[6], as[7]);
    *(float4*)(g_adst + (size_t)n * HEADS)     = make_float4(ad[0], ad[1], ad[2], ad[3]);
    *(float4*)(g_adst + (size_t)n * HEADS + 4) = make_float4(ad[4], ad[5], ad[6], ad[7]);

    float p[HEADS];
#pragma unroll
    for (int hh = 0; hh < HEADS; hh++) p[hh] = fexp(leaky(as[hh] + ad[hh]));

    float* accp = g_acc + (size_t)n * 24;
#pragma unroll
    for (int q = 0; q < 4; q++) {
        *(float4*)(accp + 4 * q) = make_float4(p[2 * q] * acc[4 * q],
                                               p[2 * q] * acc[4 * q + 1],
                                               p[2 * q + 1] * acc[4 * q + 2],
                                               p[2 * q + 1] * acc[4 * q + 3]);
    }
    *(float4*)(accp + 16) = make_float4(p[0], p[1], p[2], p[3]);
    *(float4*)(accp + 20) = make_float4(p[4], p[5], p[6], p[7]);
}

// -------- Kernel 2: per-edge gather + fast-exp + scatter (vector red) --------
// Four threads per edge: thread q in {0..3} handles heads 2q, 2q+1.
__global__ __launch_bounds__(256) void edge_kernel(const int* __restrict__ ei, int E) {
    int t = blockIdx.x * blockDim.x + threadIdx.x;
    int e = t >> 2;
    if (e >= E) return;
    int q = t & 3;
    int s = __ldg(&ei[e]);
    int d = __ldg(&ei[E + e]);

    float2 a = *(const float2*)(g_asrc + (size_t)s * HEADS + 2 * q);
    float2 b = *(const float2*)(g_adst + (size_t)d * HEADS + 2 * q);
    float p0 = fexp(leaky(a.x + b.x));
    float p1 = fexp(leaky(a.y + b.y));

    // heads 2q, 2q+1 -> values 4q..4q+3 -> half2 indices 2q, 2q+1
    uint2 hraw = *(const uint2*)(g_hh + (size_t)s * 8 + 2 * q);
    float2 f01 = __half22float2(*(__half2*)&hraw.x);
    float2 f23 = __half22float2(*(__half2*)&hraw.y);

    float* accp = g_acc + (size_t)d * 24;
    asm volatile("red.global.add.v4.f32 [%0], {%1, %2, %3, %4};"
                 :: "l"(accp + 4 * q),
                    "f"(p0 * f01.x), "f"(p0 * f01.y),
                    "f"(p1 * f23.x), "f"(p1 * f23.y) : "memory");

    // Z: pair threads (q, q^1); even-q thread issues v4 with own+partner p's.
    float pp0 = __shfl_xor_sync(0xffffffffu, p0, 1);
    float pp1 = __shfl_xor_sync(0xffffffffu, p1, 1);
    if ((q & 1) == 0) {
        asm volatile("red.global.add.v4.f32 [%0], {%1, %2, %3, %4};"
                     :: "l"(accp + 16 + 2 * q),
                        "f"(p0), "f"(p1), "f"(pp0), "f"(pp1) : "memory");
    }
}

// -------- Kernel 3: normalize + bias + FC --------
__global__ __launch_bounds__(256) void out_kernel(const float* __restrict__ bias_gat,
                                                  const float* __restrict__ W_fc,
                                                  const float* __restrict__ b_fc,
                                                  float* __restrict__ out, int N) {
    int n = blockIdx.x * blockDim.x + threadIdx.x;
    if (n >= N) return;
    const float4* ap = (const float4*)(g_acc + (size_t)n * 24);
    float4 s0 = ap[0], s1 = ap[1], s2 = ap[2], s3 = ap[3];
    float4 z0 = ap[4], z1 = ap[5];
    float S[16] = { s0.x, s0.y, s0.z, s0.w, s1.x, s1.y, s1.z, s1.w,
                    s2.x, s2.y, s2.z, s2.w, s3.x, s3.y, s3.z, s3.w };
    float Z[8]  = { z0.x, z0.y, z0.z, z0.w, z1.x, z1.y, z1.z, z1.w };

    float o0 = __ldg(&b_fc[0]), o1 = __ldg(&b_fc[1]);
#pragma unroll
    for (int hh = 0; hh < 8; hh++) {
        float inv = 1.f / Z[hh];   // Z >= exp(self-loop) > 0 always
        float g0 = S[2 * hh] * inv + __ldg(&bias_gat[2 * hh]);
        float g1 = S[2 * hh + 1] * inv + __ldg(&bias_gat[2 * hh + 1]);
        o0 += g0 * __ldg(&W_fc[(2 * hh) * 2 + 0]) + g1 * __ldg(&W_fc[(2 * hh + 1) * 2 + 0]);
        o1 += g0 * __ldg(&W_fc[(2 * hh) * 2 + 1]) + g1 * __ldg(&W_fc[(2 * hh + 1) * 2 + 1]);
    }
    ((float2*)out)[n] = make_float2(o0, o1);
}

extern "C" void kernel_launch(void* const* d_in, const int* in_sizes, int n_in,
                              void* d_out, int out_size) {
    const float* x        = (const float*)d_in[0];
    const int*   ei       = (const int*)d_in[1];   // int32 (JAX x64 disabled)
    // d_in[2] = edge_attr: unused (GATConv built without edge_dim)
    const float* W        = (const float*)d_in[3];
    const float* att_src  = (const float*)d_in[4];
    const float* att_dst  = (const float*)d_in[5];
    const float* bias_gat = (const float*)d_in[6];
    const float* W_fc     = (const float*)d_in[7];
    const float* b_fc     = (const float*)d_in[8];

    int N = in_sizes[0] / IN_F;
    int E = in_sizes[1] / 2;

    node_kernel<<<(N + NT - 1) / NT, NT>>>(x, W, att_src, att_dst, N);
    long long tthreads = 4LL * E;
    edge_kernel<<<(int)((tthreads + 255) / 256), 256>>>(ei, E);
    out_kernel<<<(N + 255) / 256, 256>>>(bias_gat, W_fc, b_fc, (float*)d_out, N);
}